// round 15
// baseline (speedup 1.0000x reference)
#include <cuda_runtime.h>

#define BQ   4096
#define TT   1024
#define DD   3
#define NBP  14      // batch pairs per block == seqs per thread (NST)
#define NST  14
#define PW   68      // W_hh shared pitch (floats): conflict-free LDS.128
#define BLK  128

typedef unsigned long long ull;

__device__ __forceinline__ ull fma2(ull a, ull b, ull c) {
    ull d;
    asm("fma.rn.f32x2 %0, %1, %2, %3;" : "=l"(d) : "l"(a), "l"(b), "l"(c));
    return d;
}
__device__ __forceinline__ float2 upk(ull a) {
    float2 v;
    asm("mov.b64 {%0, %1}, %2;" : "=f"(v.x), "=f"(v.y) : "l"(a));
    return v;
}
__device__ __forceinline__ float sigf(float x) {
    return __fdividef(1.0f, 1.0f + __expf(-x));
}
__device__ __forceinline__ float tanh_f(float x) {
    return __fdividef(2.0f, 1.0f + __expf(-2.0f * x)) - 1.0f;
}

// smem (floats): W 3*64*PW = 13056 ; hbuf 2*28*64 = 3584 ; dif 14*64 = 896 ; hid 32*14 = 448
#define SM_W     (3 * 64 * PW)
#define SM_H     (2 * 2 * NBP * 64)
#define SM_DIF   (NBP * 64)
#define SM_HID   (32 * NBP)
#define SMEM_FLOATS (SM_W + SM_H + SM_DIF + SM_HID)
#define SMEM_BYTES  (SMEM_FLOATS * 4)

__global__ void __launch_bounds__(BLK, 2) siamese_gru_kernel(
    const float* __restrict__ x1, const float* __restrict__ x2,
    const float* __restrict__ Wih, const float* __restrict__ Whh,
    const float* __restrict__ bih, const float* __restrict__ bhh,
    const float* __restrict__ W1,  const float* __restrict__ b1,
    const float* __restrict__ W2,  const float* __restrict__ b2,
    float* __restrict__ out)
{
    extern __shared__ float smem[];
    float* Wsh  = smem;
    float* hbuf = Wsh + SM_W;
    float* dif  = hbuf + SM_H;
    float* hid  = dif + SM_DIF;

    const int tid = threadIdx.x;
    const int j   = tid & 63;          // hidden unit
    const int q   = tid >> 6;          // branch: 0 -> x1, 1 -> x2
    const int bb  = blockIdx.x * NBP;

    // stage W_hh into shared: [g][row j][k], pitch PW
    for (int i = tid; i < 3 * 64 * 64; i += BLK) {
        int g = i >> 12, rem = i & 4095;
        int row = rem >> 6, k = rem & 63;
        Wsh[(g * 64 + row) * PW + k] = Whh[i];
    }
    // zero h buffer 0
    for (int i = tid; i < 2 * NBP * 64; i += BLK) hbuf[i] = 0.0f;

    // per-thread input weights/biases (unit j) in registers
    float wi[9];
#pragma unroll
    for (int g = 0; g < 3; g++)
#pragma unroll
        for (int d = 0; d < DD; d++)
            wi[g * 3 + d] = __ldg(Wih + (g * 64 + j) * DD + d);
    const float biasR  = __ldg(bih + j)       + __ldg(bhh + j);
    const float biasZ  = __ldg(bih + 64 + j)  + __ldg(bhh + 64 + j);
    const float biasN  = __ldg(bih + 128 + j);   // b_ih_n (outside r*)
    const float biasHN = __ldg(bhh + 128 + j);   // b_hh_n (inside r*)

    const float* xp = q ? x2 : x1;
    int xo[NST];
#pragma unroll
    for (int s = 0; s < NST; s++) {
        int b = bb + s;
        if (b > BQ - 1) b = BQ - 1;   // clamp OOB (duplicate work, guarded store)
        xo[s] = b * (TT * DD);
    }

    const float* Wr = Wsh + (0 * 64 + j) * PW;
    const float* Wz = Wsh + (1 * 64 + j) * PW;
    const float* Wn = Wsh + (2 * 64 + j) * PW;

    float hold[NST];
    float xf[NST][3];
#pragma unroll
    for (int s = 0; s < NST; s++) {
        hold[s] = 0.0f;
        xf[s][0] = __ldg(xp + xo[s]);
        xf[s][1] = __ldg(xp + xo[s] + 1);
        xf[s][2] = __ldg(xp + xo[s] + 2);
    }

    __syncthreads();   // weights + h0 visible

    int cur = 0;
#pragma unroll 1
    for (int t = 0; t < TT; t++) {
        const float* hc = hbuf + cur * (2 * NBP * 64) + (q * NBP) * 64;

        ull ar[NST], az[NST], an[NST];
#pragma unroll
        for (int s = 0; s < NST; s++) { ar[s] = 0ull; az[s] = 0ull; an[s] = 0ull; }

#pragma unroll 8
        for (int kk = 0; kk < 64; kk += 4) {
            ulonglong2 wr = *(const ulonglong2*)(Wr + kk);
            ulonglong2 wz = *(const ulonglong2*)(Wz + kk);
            ulonglong2 wn = *(const ulonglong2*)(Wn + kk);
#pragma unroll
            for (int s = 0; s < NST; s++) {
                ulonglong2 hv = *(const ulonglong2*)(hc + s * 64 + kk);
                ar[s] = fma2(wr.x, hv.x, ar[s]);
                ar[s] = fma2(wr.y, hv.y, ar[s]);
                az[s] = fma2(wz.x, hv.x, az[s]);
                az[s] = fma2(wz.y, hv.y, az[s]);
                an[s] = fma2(wn.x, hv.x, an[s]);
                an[s] = fma2(wn.y, hv.y, an[s]);
            }
        }

        float* hn_ = hbuf + (cur ^ 1) * (2 * NBP * 64) + (q * NBP) * 64;
#pragma unroll
        for (int s = 0; s < NST; s++) {
            float xa = xf[s][0], xd = xf[s][1], xc = xf[s][2];
            float xr = biasR + wi[0] * xa + wi[1] * xd + wi[2] * xc;
            float xz = biasZ + wi[3] * xa + wi[4] * xd + wi[5] * xc;
            float xn = biasN + wi[6] * xa + wi[7] * xd + wi[8] * xc;
            float2 vr = upk(ar[s]), vz = upk(az[s]), vn = upk(an[s]);
            float r = sigf(xr + vr.x + vr.y);
            float z = sigf(xz + vz.x + vz.y);
            float n = tanh_f(xn + r * (biasHN + vn.x + vn.y));
            float h = n + z * (hold[s] - n);
            hold[s] = h;
            hn_[s * 64 + j] = h;
        }
        // prefetch x for t+1 (consumed after next GEMV -> latency hidden)
        if (t + 1 < TT) {
            const float* xb = xp + (t + 1) * DD;
#pragma unroll
            for (int s = 0; s < NST; s++) {
                xf[s][0] = __ldg(xb + xo[s]);
                xf[s][1] = __ldg(xb + xo[s] + 1);
                xf[s][2] = __ldg(xb + xo[s] + 2);
            }
        }
        __syncthreads();   // 4 warps only — cheap
        cur ^= 1;
    }

    // --- Siamese diff + MLP head, in-block ---
    const float* hf = hbuf + cur * (2 * NBP * 64);
    for (int i = tid; i < NBP * 64; i += BLK) {
        int s = i >> 6, k = i & 63;
        dif[i] = fabsf(hf[s * 64 + k] - hf[(NBP + s) * 64 + k]);
    }
    __syncthreads();

    if (tid < 32) {
        int m = tid;
        float acc[NBP];
        float bb1 = __ldg(b1 + m);
#pragma unroll
        for (int s = 0; s < NBP; s++) acc[s] = bb1;
        for (int k = 0; k < 64; k++) {
            float w = __ldg(W1 + m * 64 + k);
#pragma unroll
            for (int s = 0; s < NBP; s++) acc[s] += w * dif[s * 64 + k];
        }
#pragma unroll
        for (int s = 0; s < NBP; s++) hid[m * NBP + s] = fmaxf(acc[s], 0.0f);
    }
    __syncthreads();

    if (tid < NBP) {
        int gb = bb + tid;
        if (gb < BQ) {
            float a = __ldg(b2);
            for (int m = 0; m < 32; m++)
                a += __ldg(W2 + m) * hid[m * NBP + tid];
            out[gb] = sigf(a);
        }
    }
}

extern "C" void kernel_launch(void* const* d_in, const int* in_sizes, int n_in,
                              void* d_out, int out_size)
{
    const float* x1  = (const float*)d_in[0];
    const float* x2  = (const float*)d_in[1];
    const float* Wih = (const float*)d_in[2];
    const float* Whh = (const float*)d_in[3];
    const float* bih = (const float*)d_in[4];
    const float* bhh = (const float*)d_in[5];
    const float* W1  = (const float*)d_in[6];
    const float* b1  = (const float*)d_in[7];
    const float* W2  = (const float*)d_in[8];
    const float* b2  = (const float*)d_in[9];
    float* out = (float*)d_out;

    cudaFuncSetAttribute(siamese_gru_kernel,
                         cudaFuncAttributeMaxDynamicSharedMemorySize, SMEM_BYTES);

    int grid = (BQ + NBP - 1) / NBP;   // 293 blocks, 2/SM (128 thr), single wave
    siamese_gru_kernel<<<grid, BLK, SMEM_BYTES>>>(
        x1, x2, Wih, Whh, bih, bhh, W1, b1, W2, b2, out);
}

// round 16
// speedup vs baseline: 1.6415x; 1.6415x over previous
#include <cuda_runtime.h>
#include <cuda_bf16.h>
#include <cstdint>

#define BQ 4096
#define TT 1024

// Pre-built B fragments for mma.sync.m16n8k16 (row.col):
// index [kt 0..4][nt 0..31][lane 0..31] -> uint4 {hi0, hi1, lo0, lo1}
// n-col = nt*8 + (lane>>2); k = kt*16 + (lane&3)*2 + {0,1,8,9}
// gate groups by n: 0-63 r, 64-127 z, 128-191 n_hidden, 192-255 n_input(x)
__device__ __align__(16) uint4 Bfrag[5 * 32 * 32];

__device__ __forceinline__ float sigf(float x) {
    return __fdividef(1.0f, 1.0f + __expf(-x));
}
__device__ __forceinline__ float tanh_f(float x) {
    return __fdividef(2.0f, 1.0f + __expf(-2.0f * x)) - 1.0f;
}
// pack (a,b) -> bf16x2 (low16 = a) plus residual pack
__device__ __forceinline__ void pack2(float a, float b, uint32_t& hi, uint32_t& lo) {
    asm("cvt.rn.bf16x2.f32 %0, %1, %2;" : "=r"(hi) : "f"(b), "f"(a));
    float fa = __uint_as_float(hi << 16);
    float fb = __uint_as_float(hi & 0xFFFF0000u);
    float ra = a - fa, rb = b - fb;
    asm("cvt.rn.bf16x2.f32 %0, %1, %2;" : "=r"(lo) : "f"(rb), "f"(ra));
}

__device__ __forceinline__ void mma_acc(float* d, const uint32_t* a, uint32_t b0, uint32_t b1) {
    asm volatile(
        "mma.sync.aligned.m16n8k16.row.col.f32.bf16.bf16.f32 "
        "{%0,%1,%2,%3}, {%4,%5,%6,%7}, {%8,%9}, {%0,%1,%2,%3};"
        : "+f"(d[0]), "+f"(d[1]), "+f"(d[2]), "+f"(d[3])
        : "r"(a[0]), "r"(a[1]), "r"(a[2]), "r"(a[3]), "r"(b0), "r"(b1));
}
__device__ __forceinline__ void mma_zero(float* d, const uint32_t* a, uint32_t b0, uint32_t b1) {
    asm volatile(
        "mma.sync.aligned.m16n8k16.row.col.f32.bf16.bf16.f32 "
        "{%0,%1,%2,%3}, {%4,%5,%6,%7}, {%8,%9}, {%10,%11,%12,%13};"
        : "=f"(d[0]), "=f"(d[1]), "=f"(d[2]), "=f"(d[3])
        : "r"(a[0]), "r"(a[1]), "r"(a[2]), "r"(a[3]), "r"(b0), "r"(b1),
          "f"(0.0f), "f"(0.0f), "f"(0.0f), "f"(0.0f));
}

// ---------- prep: build weight fragments ----------
__device__ float wval(int n, int k,
                      const float* Whh, const float* Wih,
                      const float* bih, const float* bhh) {
    int g = n >> 6, j = n & 63;
    if (k < 64)
        return (g < 3) ? Whh[(g * 64 + j) * 64 + k] : 0.0f;   // g3 (nx) has no h part
    if (k < 67) {
        int d = k - 64;
        if (g == 0) return Wih[j * 3 + d];
        if (g == 1) return Wih[(64 + j) * 3 + d];
        if (g == 3) return Wih[(128 + j) * 3 + d];
        return 0.0f;                                           // nh: no x part
    }
    if (k == 67) {
        if (g == 0) return bih[j] + bhh[j];
        if (g == 1) return bih[64 + j] + bhh[64 + j];
        if (g == 2) return bhh[128 + j];                       // inside r*( )
        return bih[128 + j];                                   // outside
    }
    return 0.0f;
}

__global__ void prep_kernel(const float* __restrict__ Whh, const float* __restrict__ Wih,
                            const float* __restrict__ bih, const float* __restrict__ bhh) {
    int i = blockIdx.x * blockDim.x + threadIdx.x;
    if (i >= 5 * 32 * 32) return;
    int lane = i & 31, nt = (i >> 5) & 31, kt = i >> 10;
    int n  = nt * 8 + (lane >> 2);
    int k0 = kt * 16 + (lane & 3) * 2;
    float v0 = wval(n, k0,     Whh, Wih, bih, bhh);
    float v1 = wval(n, k0 + 1, Whh, Wih, bih, bhh);
    float v2 = wval(n, k0 + 8, Whh, Wih, bih, bhh);
    float v3 = wval(n, k0 + 9, Whh, Wih, bih, bhh);
    uint32_t h0, l0, h1, l1;
    pack2(v0, v1, h0, l0);
    pack2(v2, v3, h1, l1);
    Bfrag[i] = make_uint4(h0, h1, l0, l1);
}

// ---------- main: persistent-register GRU, 16 seqs per warp ----------
__global__ void __launch_bounds__(128, 1) gru_mma_kernel(
    const float* __restrict__ x1, const float* __restrict__ x2,
    const float* __restrict__ W1, const float* __restrict__ b1,
    const float* __restrict__ W2, const float* __restrict__ b2,
    float* __restrict__ out)
{
    __shared__ float hbuf[64 * 64];
    __shared__ float dif[32 * 64];
    __shared__ float hidv[32 * 32];

    const int tid  = threadIdx.x;
    const int lane = tid & 31;
    const int w    = tid >> 5;
    const int grp  = lane >> 2;   // row within 16-block (and +8)
    const int quad = lane & 3;
    const int bb   = blockIdx.x * 32;     // 32 pairs per CTA
    const int cr0  = w * 16 + grp;        // CTA row of element e=0

    const float* xp[2];
#pragma unroll
    for (int e = 0; e < 2; e++) {
        int row = cr0 + e * 8;            // CTA row 0..63
        xp[e] = (row < 32) ? (x1 + (bb + row) * (TT * 3))
                           : (x2 + (bb + row - 32) * (TT * 3));
    }

    float   h[2][16];
    float   D[32][4];
    uint32_t Ahi[5][4], Alo[5][4];
#pragma unroll
    for (int e = 0; e < 2; e++)
#pragma unroll
        for (int i = 0; i < 16; i++) h[e][i] = 0.0f;
#pragma unroll
    for (int kt = 0; kt < 5; kt++)
#pragma unroll
        for (int p = 0; p < 4; p++) { Ahi[kt][p] = 0u; Alo[kt][p] = 0u; }

    // x tile for t=0
    {
        float xa[2][3];
#pragma unroll
        for (int e = 0; e < 2; e++) {
            xa[e][0] = __ldg(xp[e]); xa[e][1] = __ldg(xp[e] + 1); xa[e][2] = __ldg(xp[e] + 2);
        }
        if (quad == 0) {
            pack2(xa[0][0], xa[0][1], Ahi[4][0], Alo[4][0]);
            pack2(xa[1][0], xa[1][1], Ahi[4][1], Alo[4][1]);
        } else if (quad == 1) {
            pack2(xa[0][2], 1.0f, Ahi[4][0], Alo[4][0]);
            pack2(xa[1][2], 1.0f, Ahi[4][1], Alo[4][1]);
        }
    }

#pragma unroll 1
    for (int t = 0; t < TT; t++) {
        // ---- MMA phase: D[16x256] = A[16x80] * B, 3-term hi/lo ----
#pragma unroll
        for (int kt = 0; kt < 5; kt++) {
#pragma unroll
            for (int nt = 0; nt < 32; nt++) {
                if (kt < 4 && nt >= 24) continue;          // nx group: kt 4 only
                uint4 wf = __ldg(&Bfrag[(kt * 32 + nt) * 32 + lane]);
                if (kt == 0 || (kt == 4 && nt >= 24))
                    mma_zero(D[nt], Ahi[kt], wf.x, wf.y);
                else
                    mma_acc(D[nt], Ahi[kt], wf.x, wf.y);
                mma_acc(D[nt], Alo[kt], wf.x, wf.y);       // h_lo * W_hi
                mma_acc(D[nt], Ahi[kt], wf.z, wf.w);       // h_hi * W_lo
            }
        }

        // prefetch x for t+1
        float xa[2][3];
        if (t + 1 < TT) {
#pragma unroll
            for (int e = 0; e < 2; e++) {
                const float* p = xp[e] + (t + 1) * 3;
                xa[e][0] = __ldg(p); xa[e][1] = __ldg(p + 1); xa[e][2] = __ldg(p + 2);
            }
        }

        // ---- epilogue: gates in fp32, all in-register ----
#pragma unroll
        for (int e = 0; e < 2; e++)
#pragma unroll
            for (int ii = 0; ii < 16; ii++) {
                int jt = ii >> 1, c = ii & 1, pos = e * 2 + c;
                float r = sigf(D[jt][pos]);
                float z = sigf(D[8 + jt][pos]);
                float n = tanh_f(D[24 + jt][pos] + r * D[16 + jt][pos]);
                h[e][ii] = n + z * (h[e][ii] - n);
            }

        // ---- repack A fragments from h (exact D->A position match) ----
#pragma unroll
        for (int kt = 0; kt < 4; kt++) {
            pack2(h[0][4 * kt + 0], h[0][4 * kt + 1], Ahi[kt][0], Alo[kt][0]);
            pack2(h[1][4 * kt + 0], h[1][4 * kt + 1], Ahi[kt][1], Alo[kt][1]);
            pack2(h[0][4 * kt + 2], h[0][4 * kt + 3], Ahi[kt][2], Alo[kt][2]);
            pack2(h[1][4 * kt + 2], h[1][4 * kt + 3], Ahi[kt][3], Alo[kt][3]);
        }
        if (t + 1 < TT) {
            if (quad == 0) {
                pack2(xa[0][0], xa[0][1], Ahi[4][0], Alo[4][0]);
                pack2(xa[1][0], xa[1][1], Ahi[4][1], Alo[4][1]);
            } else if (quad == 1) {
                pack2(xa[0][2], 1.0f, Ahi[4][0], Alo[4][0]);
                pack2(xa[1][2], 1.0f, Ahi[4][1], Alo[4][1]);
            }
        }
    }

    // ---- Siamese diff + MLP head ----
#pragma unroll
    for (int e = 0; e < 2; e++)
#pragma unroll
        for (int ii = 0; ii < 16; ii++) {
            int row = cr0 + e * 8;
            int j = (ii >> 1) * 8 + quad * 2 + (ii & 1);
            hbuf[row * 64 + j] = h[e][ii];
        }
    __syncthreads();

    for (int i = tid; i < 32 * 64; i += 128) {
        int p = i >> 6, k = i & 63;
        dif[i] = fabsf(hbuf[p * 64 + k] - hbuf[(32 + p) * 64 + k]);
    }
    __syncthreads();

    {
        int m = tid & 31, pb = (tid >> 5) * 8;
        float acc[8];
        float bm = __ldg(b1 + m);
#pragma unroll
        for (int s = 0; s < 8; s++) acc[s] = bm;
        for (int k = 0; k < 64; k++) {
            float wv = __ldg(W1 + m * 64 + k);
#pragma unroll
            for (int s = 0; s < 8; s++) acc[s] += wv * dif[(pb + s) * 64 + k];
        }
#pragma unroll
        for (int s = 0; s < 8; s++) hidv[m * 32 + pb + s] = fmaxf(acc[s], 0.0f);
    }
    __syncthreads();

    if (tid < 32) {
        float a = __ldg(b2);
#pragma unroll
        for (int m = 0; m < 32; m++)
            a += __ldg(W2 + m) * hidv[m * 32 + tid];
        out[bb + tid] = sigf(a);
    }
}

extern "C" void kernel_launch(void* const* d_in, const int* in_sizes, int n_in,
                              void* d_out, int out_size)
{
    const float* x1  = (const float*)d_in[0];
    const float* x2  = (const float*)d_in[1];
    const float* Wih = (const float*)d_in[2];
    const float* Whh = (const float*)d_in[3];
    const float* bih = (const float*)d_in[4];
    const float* bhh = (const float*)d_in[5];
    const float* W1  = (const float*)d_in[6];
    const float* b1  = (const float*)d_in[7];
    const float* W2  = (const float*)d_in[8];
    const float* b2  = (const float*)d_in[9];
    float* out = (float*)d_out;

    prep_kernel<<<20, 256>>>(Whh, Wih, bih, bhh);
    gru_mma_kernel<<<BQ / 32, 128>>>(x1, x2, W1, b1, W2, b2, out);
}

// round 17
// speedup vs baseline: 2.3183x; 1.4123x over previous
#include <cuda_runtime.h>
#include <cuda_bf16.h>
#include <cstdint>

#define BQ 4096
#define TT 1024

// Pre-built B fragments for mma.sync.m16n8k16 (row.col):
// [kt 0..4][nt 0..31][lane] -> uint4 {hi0, hi1, lo0, lo1}
// n-col = nt*8 + (lane>>2); k = kt*16 + (lane&3)*2 + {0,1,8,9}
// gate groups by n: 0-63 r, 64-127 z, 128-191 n_hidden, 192-255 n_input(x)
__device__ __align__(16) uint4 Bfrag[5 * 32 * 32];

__device__ __forceinline__ float sigf(float x) {
    return __fdividef(1.0f, 1.0f + __expf(-x));
}
__device__ __forceinline__ float tanh_f(float x) {
    return __fdividef(2.0f, 1.0f + __expf(-2.0f * x)) - 1.0f;
}
// pack (a,b) -> bf16x2 (low16 = a) plus residual pack
__device__ __forceinline__ void pack2(float a, float b, uint32_t& hi, uint32_t& lo) {
    asm("cvt.rn.bf16x2.f32 %0, %1, %2;" : "=r"(hi) : "f"(b), "f"(a));
    float fa = __uint_as_float(hi << 16);
    float fb = __uint_as_float(hi & 0xFFFF0000u);
    float ra = a - fa, rb = b - fb;
    asm("cvt.rn.bf16x2.f32 %0, %1, %2;" : "=r"(lo) : "f"(rb), "f"(ra));
}

__device__ __forceinline__ void mma_acc(float* d, const uint32_t* a, uint32_t b0, uint32_t b1) {
    asm volatile(
        "mma.sync.aligned.m16n8k16.row.col.f32.bf16.bf16.f32 "
        "{%0,%1,%2,%3}, {%4,%5,%6,%7}, {%8,%9}, {%0,%1,%2,%3};"
        : "+f"(d[0]), "+f"(d[1]), "+f"(d[2]), "+f"(d[3])
        : "r"(a[0]), "r"(a[1]), "r"(a[2]), "r"(a[3]), "r"(b0), "r"(b1));
}
__device__ __forceinline__ void mma_zero(float* d, const uint32_t* a, uint32_t b0, uint32_t b1) {
    asm volatile(
        "mma.sync.aligned.m16n8k16.row.col.f32.bf16.bf16.f32 "
        "{%0,%1,%2,%3}, {%4,%5,%6,%7}, {%8,%9}, {%10,%11,%12,%13};"
        : "=f"(d[0]), "=f"(d[1]), "=f"(d[2]), "=f"(d[3])
        : "r"(a[0]), "r"(a[1]), "r"(a[2]), "r"(a[3]), "r"(b0), "r"(b1),
          "f"(0.0f), "f"(0.0f), "f"(0.0f), "f"(0.0f));
}
// 3-term hi/lo product into accumulator (zero-init variant for first K-slice)
__device__ __forceinline__ void mma3(float* d, const uint32_t* ahi, const uint32_t* alo,
                                     uint4 wf, bool first) {
    if (first) mma_zero(d, ahi, wf.x, wf.y);
    else       mma_acc(d, ahi, wf.x, wf.y);
    mma_acc(d, alo, wf.x, wf.y);   // h_lo * W_hi
    mma_acc(d, ahi, wf.z, wf.w);   // h_hi * W_lo
}

// ---------- prep: build weight fragments ----------
__device__ float wval(int n, int k,
                      const float* Whh, const float* Wih,
                      const float* bih, const float* bhh) {
    int g = n >> 6, j = n & 63;
    if (k < 64)
        return (g < 3) ? Whh[(g * 64 + j) * 64 + k] : 0.0f;   // nx has no h part
    if (k < 67) {
        int d = k - 64;
        if (g == 0) return Wih[j * 3 + d];
        if (g == 1) return Wih[(64 + j) * 3 + d];
        if (g == 3) return Wih[(128 + j) * 3 + d];
        return 0.0f;                                           // nh: no x part
    }
    if (k == 67) {
        if (g == 0) return bih[j] + bhh[j];
        if (g == 1) return bih[64 + j] + bhh[64 + j];
        if (g == 2) return bhh[128 + j];                       // inside r*( )
        return bih[128 + j];                                   // outside
    }
    return 0.0f;
}

__global__ void prep_kernel(const float* __restrict__ Whh, const float* __restrict__ Wih,
                            const float* __restrict__ bih, const float* __restrict__ bhh) {
    int i = blockIdx.x * blockDim.x + threadIdx.x;
    if (i >= 5 * 32 * 32) return;
    int lane = i & 31, nt = (i >> 5) & 31, kt = i >> 10;
    int n  = nt * 8 + (lane >> 2);
    int k0 = kt * 16 + (lane & 3) * 2;
    float v0 = wval(n, k0,     Whh, Wih, bih, bhh);
    float v1 = wval(n, k0 + 1, Whh, Wih, bih, bhh);
    float v2 = wval(n, k0 + 8, Whh, Wih, bih, bhh);
    float v3 = wval(n, k0 + 9, Whh, Wih, bih, bhh);
    uint32_t h0, l0, h1, l1;
    pack2(v0, v1, h0, l0);
    pack2(v2, v3, h1, l1);
    Bfrag[i] = make_uint4(h0, h1, l0, l1);
}

// ---------- main: 16 seqs per CTA, 4 warps split the 64 j-columns ----------
#define HP 68   // hx pitch (floats): conflict-free for strided row reads

__global__ void __launch_bounds__(128, 4) gru_mma_kernel(
    const float* __restrict__ x1, const float* __restrict__ x2,
    const float* __restrict__ W1, const float* __restrict__ b1,
    const float* __restrict__ W2, const float* __restrict__ b2,
    float* __restrict__ out)
{
    __shared__ float hx[2][16 * HP];
    __shared__ float dif[8 * 64];
    __shared__ float hidv[32 * 8];

    const int tid  = threadIdx.x;
    const int lane = tid & 31;
    const int w    = tid >> 5;
    const int grp  = lane >> 2;
    const int quad = lane & 3;
    const int bb8  = blockIdx.x * 8;      // 8 pairs per CTA; rows 0-7 x1, 8-15 x2

    const float* xp0 = x1 + (bb8 + grp) * (TT * 3);   // row grp   (e=0)
    const float* xp1 = x2 + (bb8 + grp) * (TT * 3);   // row grp+8 (e=1)

    uint32_t Ahi[5][4], Alo[5][4];
    float h[2][4];                        // [j2][e*2+c] : hprev at this thread's D positions
#pragma unroll
    for (int kt = 0; kt < 5; kt++)
#pragma unroll
        for (int p = 0; p < 4; p++) { Ahi[kt][p] = 0u; Alo[kt][p] = 0u; }
#pragma unroll
    for (int j2 = 0; j2 < 2; j2++)
#pragma unroll
        for (int p = 0; p < 4; p++) h[j2][p] = 0.0f;

    // x tile for t=0 (k 64..67 = xa,xb,xc,1 ; rest zero)
    {
        float a0 = __ldg(xp0), b0 = __ldg(xp0 + 1), c0 = __ldg(xp0 + 2);
        float a1 = __ldg(xp1), b1_ = __ldg(xp1 + 1), c1 = __ldg(xp1 + 2);
        if (quad == 0) {
            pack2(a0, b0, Ahi[4][0], Alo[4][0]);
            pack2(a1, b1_, Ahi[4][1], Alo[4][1]);
        } else if (quad == 1) {
            pack2(c0, 1.0f, Ahi[4][0], Alo[4][0]);
            pack2(c1, 1.0f, Ahi[4][1], Alo[4][1]);
        }
    }

#pragma unroll 1
    for (int t = 0; t < TT; t++) {
        float Dr[2][4], Dz[2][4], Dn[2][4], Dx[2][4];

#pragma unroll
        for (int kt = 0; kt < 5; kt++) {
#pragma unroll
            for (int j2 = 0; j2 < 2; j2++) {
                const int jt = (w << 1) | j2;
                uint4 wf;
                wf = __ldg(&Bfrag[(kt * 32 + jt) * 32 + lane]);          // r
                mma3(Dr[j2], Ahi[kt], Alo[kt], wf, kt == 0);
                wf = __ldg(&Bfrag[(kt * 32 + 8 + jt) * 32 + lane]);      // z
                mma3(Dz[j2], Ahi[kt], Alo[kt], wf, kt == 0);
                wf = __ldg(&Bfrag[(kt * 32 + 16 + jt) * 32 + lane]);     // n_h
                mma3(Dn[j2], Ahi[kt], Alo[kt], wf, kt == 0);
                if (kt == 4) {
                    wf = __ldg(&Bfrag[(4 * 32 + 24 + jt) * 32 + lane]);  // n_x (+bias)
                    mma3(Dx[j2], Ahi[4], Alo[4], wf, true);
                }
            }
        }

        // prefetch x for t+1
        float a0, b0, c0, a1, b1_, c1;
        const bool dox = (t + 1 < TT);
        if (dox) {
            const float* p0 = xp0 + (t + 1) * 3;
            const float* p1 = xp1 + (t + 1) * 3;
            a0 = __ldg(p0); b0 = __ldg(p0 + 1); c0 = __ldg(p0 + 2);
            a1 = __ldg(p1); b1_ = __ldg(p1 + 1); c1 = __ldg(p1 + 2);
        }

        // epilogue: gates in fp32, write h slice to smem
        float* hxb = hx[t & 1];
#pragma unroll
        for (int j2 = 0; j2 < 2; j2++)
#pragma unroll
            for (int e = 0; e < 2; e++)
#pragma unroll
                for (int c = 0; c < 2; c++) {
                    int pos = e * 2 + c;
                    float r = sigf(Dr[j2][pos]);
                    float z = sigf(Dz[j2][pos]);
                    float n = tanh_f(Dx[j2][pos] + r * Dn[j2][pos]);
                    float hv = n + z * (h[j2][pos] - n);
                    h[j2][pos] = hv;
                    int row = grp + e * 8;
                    int col = (((w << 1) | j2) << 3) + (quad << 1) + c;
                    hxb[row * HP + col] = hv;
                }
        __syncthreads();

        // rebuild full A fragments from exchanged h
#pragma unroll
        for (int kt = 0; kt < 4; kt++) {
            int k0 = kt * 16 + (quad << 1);
            float2 v00 = *(const float2*)&hxb[grp * HP + k0];
            float2 v01 = *(const float2*)&hxb[grp * HP + k0 + 8];
            float2 v10 = *(const float2*)&hxb[(grp + 8) * HP + k0];
            float2 v11 = *(const float2*)&hxb[(grp + 8) * HP + k0 + 8];
            pack2(v00.x, v00.y, Ahi[kt][0], Alo[kt][0]);
            pack2(v10.x, v10.y, Ahi[kt][1], Alo[kt][1]);
            pack2(v01.x, v01.y, Ahi[kt][2], Alo[kt][2]);
            pack2(v11.x, v11.y, Ahi[kt][3], Alo[kt][3]);
        }
        if (dox) {
            if (quad == 0) {
                pack2(a0, b0, Ahi[4][0], Alo[4][0]);
                pack2(a1, b1_, Ahi[4][1], Alo[4][1]);
            } else if (quad == 1) {
                pack2(c0, 1.0f, Ahi[4][0], Alo[4][0]);
                pack2(c1, 1.0f, Ahi[4][1], Alo[4][1]);
            }
        }
    }

    // ---- Siamese diff + MLP head (h final is in hx[1]) ----
    const float* hp = hx[(TT - 1) & 1];
    for (int i = tid; i < 8 * 64; i += 128) {
        int p = i >> 6, k = i & 63;
        dif[i] = fabsf(hp[p * HP + k] - hp[(8 + p) * HP + k]);
    }
    __syncthreads();

    if (tid < 32) {
        int m = tid;
        float acc[8];
        float bm = __ldg(b1 + m);
#pragma unroll
        for (int s = 0; s < 8; s++) acc[s] = bm;
        for (int k = 0; k < 64; k++) {
            float wv = __ldg(W1 + m * 64 + k);
#pragma unroll
            for (int s = 0; s < 8; s++) acc[s] += wv * dif[s * 64 + k];
        }
#pragma unroll
        for (int s = 0; s < 8; s++) hidv[m * 8 + s] = fmaxf(acc[s], 0.0f);
    }
    __syncthreads();

    if (tid < 8) {
        float a = __ldg(b2);
#pragma unroll
        for (int m = 0; m < 32; m++)
            a += __ldg(W2 + m) * hidv[m * 8 + tid];
        out[bb8 + tid] = sigf(a);
    }
}

extern "C" void kernel_launch(void* const* d_in, const int* in_sizes, int n_in,
                              void* d_out, int out_size)
{
    const float* x1  = (const float*)d_in[0];
    const float* x2  = (const float*)d_in[1];
    const float* Wih = (const float*)d_in[2];
    const float* Whh = (const float*)d_in[3];
    const float* bih = (const float*)d_in[4];
    const float* bhh = (const float*)d_in[5];
    const float* W1  = (const float*)d_in[6];
    const float* b1  = (const float*)d_in[7];
    const float* W2  = (const float*)d_in[8];
    const float* b2  = (const float*)d_in[9];
    float* out = (float*)d_out;

    prep_kernel<<<20, 256>>>(Whh, Wih, bih, bhh);
    gru_mma_kernel<<<BQ / 8, 128>>>(x1, x2, W1, b1, W2, b2, out);
}